// round 7
// baseline (speedup 1.0000x reference)
#include <cuda_runtime.h>
#include <cuda_fp16.h>
#include <cstdint>

// ---------------- problem constants ----------------
#define KH_ 9
#define KW_ 9
#define IC_ 25
#define OC_ 100
#define H_  256
#define W_  256
#define OH_ 248
#define OW_ 248
#define B_  8

// ---------------- GEMM config ----------------
#define KWP 10            // kw padded 9 -> 10 (keeps even-k pairs intra-row & aligned)
#define NOC 128           // oc padded 100 -> 128 (16 n8 chunks; 8 per warp-column)
#define MT  128           // pixels per tile
#define APITCH 144        // fp16 elems per ic row (>=137)
#define AROWB (APITCH*2)  // 288 B
#define BPITCH 264        // fp16 elems per oc row (k: 25*10=250 -> 264 pad)
#define BROWB (BPITCH*2)  // 528 B (132 words = 4-bank stride -> conflict-free)
#define NTHR 256
#define NAROWS 26         // 25 ic + 1 zero row for k-pad region (k 250..255 -> ic 25)

// smem layout (bytes)
#define SM_BIAS 0
#define SM_A    512
#define SM_AO   (SM_A + NAROWS*AROWB)       // odd-shift copy
#define SM_B    (SM_A + 2*NAROWS*AROWB)     // 512 + 14976 = 15488
#define SMEM_TOTAL (SM_B + NOC*BROWB)       // 15488 + 67584 = 83072 -> 2 CTAs/SM

// pre-split, pre-padded weights: [kh][hi/lo][oc][k = ic*10+kw]
__device__ __align__(16) __half g_w[KH_][2][NOC][BPITCH];

// ---------------- helpers ----------------
__device__ __forceinline__ uint32_t smem_u32(const void* p) {
    uint32_t a;
    asm("{ .reg .u64 t; cvta.to.shared.u64 t, %1; cvt.u32.u64 %0, t; }" : "=r"(a) : "l"(p));
    return a;
}

__device__ __forceinline__ uint32_t lds32(uint32_t a) {
    uint32_t v;
    asm volatile("ld.shared.b32 %0, [%1];" : "=r"(v) : "r"(a));
    return v;
}

__device__ __forceinline__ void ldmx4(uint32_t& r0, uint32_t& r1, uint32_t& r2,
                                      uint32_t& r3, uint32_t addr) {
    asm volatile("ldmatrix.sync.aligned.m8n8.x4.shared.b16 {%0,%1,%2,%3}, [%4];"
                 : "=r"(r0), "=r"(r1), "=r"(r2), "=r"(r3) : "r"(addr));
}

__device__ __forceinline__ void mma16816(float* d, const uint32_t* a,
                                         uint32_t b0, uint32_t b1) {
    asm volatile(
        "mma.sync.aligned.m16n8k16.row.col.f32.f16.f16.f32 "
        "{%0,%1,%2,%3}, {%4,%5,%6,%7}, {%8,%9}, {%0,%1,%2,%3};"
        : "+f"(d[0]), "+f"(d[1]), "+f"(d[2]), "+f"(d[3])
        : "r"(a[0]), "r"(a[1]), "r"(a[2]), "r"(a[3]), "r"(b0), "r"(b1));
}

// ---------------- weight prep ----------------
__global__ void prep_w(const float* __restrict__ wt) {
    int idx = blockIdx.x * blockDim.x + threadIdx.x;
    if (idx >= KH_ * NOC * BPITCH) return;
    int kh = idx / (NOC * BPITCH);
    int r  = idx % (NOC * BPITCH);
    int oc = r / BPITCH;
    int k  = r % BPITCH;
    float w = 0.f;
    if (oc < OC_ && k < IC_ * KWP) {
        int ic = k / KWP, kw = k % KWP;
        if (kw < KW_)
            w = wt[(((size_t)oc * IC_ + ic) * KH_ + kh) * KW_ + kw];
    }
    __half hi = __float2half_rn(w);
    __half lo = __float2half_rn(w - __half2float(hi));
    g_w[kh][0][oc][k] = hi;
    g_w[kh][1][oc][k] = lo;
}

// ---------------- main kernel ----------------
// block = 128 px x 128 oc(pad) of one output row (b, y).
// 8 warps: wm = wid&3 (2 m16-frags), wn = wid>>2 (8 n8-chunks via 4 ldmatrix.x4).
__global__ __launch_bounds__(NTHR, 2)
void conv_hmma(const float* __restrict__ in,
               const float* __restrict__ bias,
               float* __restrict__ out) {
    extern __shared__ char smem[];
    const uint32_t sb = smem_u32(smem);
    const int tid = threadIdx.x;
    const int lid = tid & 31;
    const int wid = tid >> 5;
    const int wm = wid & 3;
    const int wn = wid >> 2;
    const int g  = lid >> 2;          // 0..7
    const int c4 = (lid & 3) << 1;    // k-pair base 0,2,4,6
    const int x0 = blockIdx.x ? (OW_ - MT) : 0;   // 0 or 120
    const int y  = blockIdx.y;
    const int b  = blockIdx.z;

    // zero A buffers (pads + zero row persist) + stage bias
#pragma unroll 1
    for (int i = tid; i < (2 * NAROWS * AROWB) / 16; i += NTHR)
        *(uint4*)(smem + SM_A + i * 16) = make_uint4(0, 0, 0, 0);
    if (tid < NOC)
        *(float*)(smem + SM_BIAS + tid * 4) = (tid < OC_) ? bias[tid] : 0.f;
    __syncthreads();

    // A per-thread row bases (parity of px == parity of g)
    const uint32_t abase = sb + ((g & 1) ? (SM_AO - 2) : SM_A);
    uint32_t apx[2][2];
#pragma unroll
    for (int m = 0; m < 2; ++m)
#pragma unroll
        for (int h = 0; h < 2; ++h)
            apx[m][h] = abase + (uint32_t)(((wm * 2 + m) * 16 + g + h * 8) * 2);

    // ldmatrix base addresses: 4 x4-loads cover nc pairs (0,1)(2,3)(4,5)(6,7)
    // thread role: grp = lid>>3 (tile), t = lid&7 (row in tile)
    //   tile row  = (wn*8 + 2*j + (grp>>1))*8 + t
    //   tile koff = (grp&1)*8 halves = (grp&1)*16 bytes
    const int grp = lid >> 3;
    const int tr  = lid & 7;
    uint32_t bld[4];
#pragma unroll
    for (int j = 0; j < 4; ++j)
        bld[j] = sb + SM_B
               + (uint32_t)(((wn * 8 + 2 * j + (grp >> 1)) * 8 + tr) * BROWB
                            + (grp & 1) * 16);

    float acc[2][8][4];
#pragma unroll
    for (int m = 0; m < 2; ++m)
#pragma unroll
        for (int n = 0; n < 8; ++n)
#pragma unroll
            for (int q = 0; q < 4; ++q)
                acc[m][n][q] = 0.f;

#pragma unroll 1
    for (int kh = 0; kh < KH_; ++kh) {
#pragma unroll 1
        for (int pass = 0; pass < 2; ++pass) {
            __syncthreads();   // previous compute done with A/B buffers

            // ---- stage B(kh, pass) via cp.async ----
            {
                const char* src = (const char*)(&g_w[kh][pass][0][0]);
                const uint32_t dst = sb + SM_B;
#pragma unroll 1
                for (int i = tid; i < (NOC * BROWB) / 16; i += NTHR) {
                    asm volatile("cp.async.cg.shared.global [%0], [%1], 16;"
                                 :: "r"(dst + (uint32_t)(i * 16)), "l"(src + i * 16));
                }
                asm volatile("cp.async.commit_group;" ::: "memory");
            }
            // ---- stage A row images (when kh advances), overlapped with cp.async ----
            if (pass == 0 && tid < MT + KW_ - 1) {  // tid 0..135
                const float* rp = in + (((size_t)(b * IC_)) * H_ + (size_t)(y + kh)) * W_
                                  + x0 + tid;
#pragma unroll 1
                for (int ic = 0; ic < IC_; ++ic) {
                    float v = rp[(size_t)ic * (H_ * W_)];
                    __half hv = __float2half_rn(v);
                    *(__half*)(smem + SM_A + ic * AROWB + tid * 2) = hv;
                    if (tid > 0)
                        *(__half*)(smem + SM_AO + ic * AROWB + (tid - 1) * 2) = hv;
                }
            }
            asm volatile("cp.async.wait_group 0;" ::: "memory");
            __syncthreads();

            // ---- compute: 16 k16 chunks ----
#pragma unroll 1
            for (int kc = 0; kc < 16; ++kc) {
                const int k0 = kc * 16 + c4;
                const int k1 = k0 + 8;
                const int ic0 = (k0 * 6554) >> 16;   // /10
                const int ic1 = (k1 * 6554) >> 16;
                const uint32_t koff0 = (uint32_t)(ic0 * AROWB + (k0 - ic0 * KWP) * 2);
                const uint32_t koff1 = (uint32_t)(ic1 * AROWB + (k1 - ic1 * KWP) * 2);

                uint32_t a[2][4];
#pragma unroll
                for (int m = 0; m < 2; ++m) {
                    a[m][0] = lds32(apx[m][0] + koff0);
                    a[m][1] = lds32(apx[m][1] + koff0);
                    a[m][2] = lds32(apx[m][0] + koff1);
                    a[m][3] = lds32(apx[m][1] + koff1);
                }

                const uint32_t kb = (uint32_t)(kc * 32);
#pragma unroll
                for (int j = 0; j < 4; ++j) {
                    uint32_t b0, b1, b2, b3;
                    ldmx4(b0, b1, b2, b3, bld[j] + kb);
                    mma16816(acc[0][2 * j],     a[0], b0, b1);
                    mma16816(acc[1][2 * j],     a[1], b0, b1);
                    mma16816(acc[0][2 * j + 1], a[0], b2, b3);
                    mma16816(acc[1][2 * j + 1], a[1], b2, b3);
                }
            }
        }
    }

    // ---- epilogue: bias + stores (px in range; guard oc) ----
#pragma unroll
    for (int m = 0; m < 2; ++m) {
        const int px = (wm * 2 + m) * 16 + g;
#pragma unroll
        for (int nc = 0; nc < 8; ++nc) {
            const int oc = (wn * 8 + nc) * 8 + c4;
            if (oc < OC_) {
                float bz0 = *(float*)(smem + SM_BIAS + oc * 4);
                float bz1 = *(float*)(smem + SM_BIAS + (oc + 1) * 4);
                size_t base0 = (((size_t)(b * OC_ + oc)) * OH_ + y) * OW_ + x0;
                size_t base1 = base0 + (size_t)OH_ * OW_;
                out[base0 + px]     = acc[m][nc][0] + bz0;
                out[base1 + px]     = acc[m][nc][1] + bz1;
                out[base0 + px + 8] = acc[m][nc][2] + bz0;
                out[base1 + px + 8] = acc[m][nc][3] + bz1;
            }
        }
    }
}

// ---------------- launch ----------------
extern "C" void kernel_launch(void* const* d_in, const int* in_sizes, int n_in,
                              void* d_out, int out_size) {
    const float* pic  = (const float*)d_in[0];   // [8,25,256,256]
    const float* wt   = (const float*)d_in[1];   // [100,25,9,9]
    const float* bias = (const float*)d_in[2];   // [100]
    float* out = (float*)d_out;                  // [8,100,248,248]

    int n = KH_ * NOC * BPITCH;
    prep_w<<<(n + 255) / 256, 256>>>(wt);

    cudaFuncSetAttribute(conv_hmma, cudaFuncAttributeMaxDynamicSharedMemorySize, SMEM_TOTAL);
    dim3 grid(2, OH_, B_);
    conv_hmma<<<grid, NTHR, SMEM_TOTAL>>>(pic, bias, out);
}

// round 8
// speedup vs baseline: 1.2047x; 1.2047x over previous
#include <cuda_runtime.h>
#include <cuda_fp16.h>
#include <cstdint>

// ---------------- problem constants ----------------
#define KH_ 9
#define KW_ 9
#define IC_ 25
#define OC_ 100
#define H_  256
#define W_  256
#define OH_ 248
#define OW_ 248
#define B_  8

// ---------------- GEMM config ----------------
#define KWP 10            // kw padded 9 -> 10
#define NOC 112           // oc padded 100 -> 112 (14 n8 chunks; 7 per warp-column)
#define MT  128           // pixels per tile
#define APITCH 144        // fp16 elems per ic row
#define AROWB (APITCH*2)  // 288 B
#define NTHR 256
#define NAROWS 26         // 25 ic + zero row for k-pad (k 250..255 -> ic 25)

// B quarter tiles: 64 k-elems, pitch 72 elems = 144 B (16B aligned, 4-bank stride)
#define QPITCH 72
#define QROWB  144
#define QTILE  (NOC*QROWB)       // 16128 B
#define NSEG   72                // 9 kh * 2 pass * 4 quarters

// A buffer: even copy + odd-shift copy
#define ACOPY (NAROWS*AROWB)     // 7488
#define ABUF  (2*ACOPY)          // 14976

// smem layout (bytes)
#define SM_BIAS 0
#define SM_A    512                         // two A buffers (kh parity)
#define SM_B    (SM_A + 2*ABUF)             // 512 + 29952 = 30464
#define SMEM_TOTAL (SM_B + 3*QTILE)         // 30464 + 48384 = 78848 -> 2 CTAs/SM

// pre-split weights: [kh][hi/lo][quarter][oc][k_local(72)]
__device__ __align__(16) __half g_w[KH_][2][4][NOC][QPITCH];

// ---------------- helpers ----------------
__device__ __forceinline__ uint32_t smem_u32(const void* p) {
    uint32_t a;
    asm("{ .reg .u64 t; cvta.to.shared.u64 t, %1; cvt.u32.u64 %0, t; }" : "=r"(a) : "l"(p));
    return a;
}

__device__ __forceinline__ uint32_t lds32(uint32_t a) {
    uint32_t v;
    asm volatile("ld.shared.b32 %0, [%1];" : "=r"(v) : "r"(a));
    return v;
}

__device__ __forceinline__ void ldmx4(uint32_t& r0, uint32_t& r1, uint32_t& r2,
                                      uint32_t& r3, uint32_t addr) {
    asm volatile("ldmatrix.sync.aligned.m8n8.x4.shared.b16 {%0,%1,%2,%3}, [%4];"
                 : "=r"(r0), "=r"(r1), "=r"(r2), "=r"(r3) : "r"(addr));
}

__device__ __forceinline__ void ldmx2(uint32_t& r0, uint32_t& r1, uint32_t addr) {
    asm volatile("ldmatrix.sync.aligned.m8n8.x2.shared.b16 {%0,%1}, [%2];"
                 : "=r"(r0), "=r"(r1) : "r"(addr));
}

__device__ __forceinline__ void mma16816(float* d, const uint32_t* a,
                                         uint32_t b0, uint32_t b1) {
    asm volatile(
        "mma.sync.aligned.m16n8k16.row.col.f32.f16.f16.f32 "
        "{%0,%1,%2,%3}, {%4,%5,%6,%7}, {%8,%9}, {%0,%1,%2,%3};"
        : "+f"(d[0]), "+f"(d[1]), "+f"(d[2]), "+f"(d[3])
        : "r"(a[0]), "r"(a[1]), "r"(a[2]), "r"(a[3]), "r"(b0), "r"(b1));
}

// ---------------- weight prep ----------------
__global__ void prep_w(const float* __restrict__ wt) {
    int idx = blockIdx.x * blockDim.x + threadIdx.x;
    const int n = KH_ * 2 * 4 * NOC * QPITCH;
    if (idx >= n) return;
    int kh   = idx / (2 * 4 * NOC * QPITCH);
    int rem  = idx % (2 * 4 * NOC * QPITCH);
    int pass = rem / (4 * NOC * QPITCH);  rem %= (4 * NOC * QPITCH);
    int q    = rem / (NOC * QPITCH);      rem %= (NOC * QPITCH);
    int oc   = rem / QPITCH;
    int kl   = rem % QPITCH;
    float w = 0.f;
    int k = q * 64 + kl;
    if (oc < OC_ && kl < 64 && k < IC_ * KWP) {
        int ic = k / KWP, kw = k % KWP;
        if (kw < KW_)
            w = wt[(((size_t)oc * IC_ + ic) * KH_ + kh) * KW_ + kw];
    }
    __half hi = __float2half_rn(w);
    if (pass == 0) {
        g_w[kh][0][q][oc][kl] = hi;
    } else {
        g_w[kh][1][q][oc][kl] = __float2half_rn(w - __half2float(hi));
    }
}

// ---------------- main kernel ----------------
// block = 128 px x 112 oc of one output row (b, y).
// 8 warps: wm = wid&3 (2 m16-frags), wn = wid>>2 (7 n8-chunks).
// 72 pipelined segments: seg s -> kh=s>>3, pass=(s>>2)&1, quarter=s&3.
__global__ __launch_bounds__(NTHR, 2)
void conv_hmma(const float* __restrict__ in,
               const float* __restrict__ bias,
               float* __restrict__ out) {
    extern __shared__ char smem[];
    const uint32_t sb = smem_u32(smem);
    const int tid = threadIdx.x;
    const int lid = tid & 31;
    const int wid = tid >> 5;
    const int wm = wid & 3;
    const int wn = wid >> 2;
    const int g  = lid >> 2;          // 0..7
    const int c4 = (lid & 3) << 1;    // 0,2,4,6
    const int x0 = blockIdx.x ? (OW_ - MT) : 0;
    const int y  = blockIdx.y;
    const int b  = blockIdx.z;

    // ---- init: zero both A buffers, stage bias ----
#pragma unroll 1
    for (int i = tid; i < (2 * ABUF) / 16; i += NTHR)
        *(uint4*)(smem + SM_A + i * 16) = make_uint4(0, 0, 0, 0);
    if (tid < NOC)
        *(float*)(smem + SM_BIAS + tid * 4) = (tid < OC_) ? bias[tid] : 0.f;
    __syncthreads();

    // ---- prologue: stage A(kh=0) into abuf0 ----
    {
        char* ab = smem + SM_A;   // buffer 0
#pragma unroll 1
        for (int i = tid; i < IC_ * 136; i += NTHR) {
            int row = i / 136, col = i % 136;
            float v = in[(((size_t)(b * IC_ + row)) * H_ + y) * W_ + x0 + col];
            __half hv = __float2half_rn(v);
            *(__half*)(ab + row * AROWB + col * 2) = hv;
            if (col > 0)
                *(__half*)(ab + ACOPY + row * AROWB + (col - 1) * 2) = hv;
        }
    }
    // ---- prologue: issue B groups for segments 0 and 1 ----
#pragma unroll
    for (int s = 0; s < 2; ++s) {
        const char* src = (const char*)(&g_w[0][0][s][0][0]);
        const uint32_t dst = sb + SM_B + (uint32_t)(s * QTILE);
#pragma unroll 1
        for (int i = tid; i < QTILE / 16; i += NTHR)
            asm volatile("cp.async.cg.shared.global [%0], [%1], 16;"
                         :: "r"(dst + (uint32_t)(i * 16)), "l"(src + i * 16));
        asm volatile("cp.async.commit_group;" ::: "memory");
    }

    // ldmatrix per-thread row/koff components (within a quarter tile)
    const int grp = lid >> 3;      // 0..3
    const int tr  = lid & 7;
    uint32_t bro[3];
#pragma unroll
    for (int j = 0; j < 3; ++j)
        bro[j] = (uint32_t)(((wn * 7 + 2 * j + (grp >> 1)) * 8 + tr) * QROWB
                            + (grp & 1) * 16);
    const uint32_t brx = (uint32_t)(((wn * 7 + 6) * 8 + (lid & 7)) * QROWB
                                    + ((lid >> 3) & 1) * 16);

    float acc[2][7][4];
#pragma unroll
    for (int m = 0; m < 2; ++m)
#pragma unroll
        for (int n = 0; n < 7; ++n)
#pragma unroll
            for (int q = 0; q < 4; ++q)
                acc[m][n][q] = 0.f;

    // ---- pipelined main loop ----
#pragma unroll 1
    for (int s = 0; s < NSEG; ++s) {
        const int kh   = s >> 3;
        const int qr   = s & 3;
        const bool do_apref = ((s & 4) == 0) && (qr < 2) && (kh < 8);

        if (s < NSEG - 2) {
            asm volatile("cp.async.wait_group 1;" ::: "memory");
        } else {
            asm volatile("cp.async.wait_group 0;" ::: "memory");
        }
        __syncthreads();

        // issue B prefetch for segment s+2 into ring slot (s+2)%3
        if (s + 2 < NSEG) {
            const int s2 = s + 2;
            const char* src = (const char*)(&g_w[s2 >> 3][(s2 >> 2) & 1][s2 & 3][0][0]);
            const uint32_t dst = sb + SM_B + (uint32_t)(((s2) % 3) * QTILE);
#pragma unroll 1
            for (int i = tid; i < QTILE / 16; i += NTHR)
                asm volatile("cp.async.cg.shared.global [%0], [%1], 16;"
                             :: "r"(dst + (uint32_t)(i * 16)), "l"(src + i * 16));
            asm volatile("cp.async.commit_group;" ::: "memory");
        }

        // A(kh+1) prefetch: LDG phase (before compute; STS after compute)
        float fpref[7];
        if (do_apref) {
            const int base = qr * 1792;
#pragma unroll
            for (int j = 0; j < 7; ++j) {
                int i = base + j * NTHR + tid;
                fpref[j] = 0.f;
                if (i < IC_ * 136) {
                    int row = i / 136, col = i % 136;
                    fpref[j] = in[(((size_t)(b * IC_ + row)) * H_ + (y + kh + 1)) * W_
                                  + x0 + col];
                }
            }
        }

        // ---- compute: 4 kc chunks on quarter qr ----
        const uint32_t abufb = sb + SM_A + (uint32_t)((kh & 1) * ABUF);
        const uint32_t abase = abufb + ((g & 1) ? (uint32_t)(ACOPY - 2) : 0u);
        uint32_t apx[2][2];
#pragma unroll
        for (int m = 0; m < 2; ++m)
#pragma unroll
            for (int h = 0; h < 2; ++h)
                apx[m][h] = abase + (uint32_t)(((wm * 2 + m) * 16 + g + h * 8) * 2);

        const uint32_t qb = sb + SM_B + (uint32_t)((s % 3) * QTILE);

#pragma unroll
        for (int kc = 0; kc < 4; ++kc) {
            const int k0 = qr * 64 + kc * 16 + c4;
            const int k1 = k0 + 8;
            const int ic0 = (k0 * 6554) >> 16;   // /10
            const int ic1 = (k1 * 6554) >> 16;
            const uint32_t koff0 = (uint32_t)(ic0 * AROWB + (k0 - ic0 * KWP) * 2);
            const uint32_t koff1 = (uint32_t)(ic1 * AROWB + (k1 - ic1 * KWP) * 2);

            uint32_t a[2][4];
#pragma unroll
            for (int m = 0; m < 2; ++m) {
                a[m][0] = lds32(apx[m][0] + koff0);
                a[m][1] = lds32(apx[m][1] + koff0);
                a[m][2] = lds32(apx[m][0] + koff1);
                a[m][3] = lds32(apx[m][1] + koff1);
            }

            const uint32_t kb = (uint32_t)(kc * 32);
#pragma unroll
            for (int j = 0; j < 3; ++j) {
                uint32_t b0, b1, b2, b3;
                ldmx4(b0, b1, b2, b3, qb + bro[j] + kb);
                mma16816(acc[0][2 * j],     a[0], b0, b1);
                mma16816(acc[1][2 * j],     a[1], b0, b1);
                mma16816(acc[0][2 * j + 1], a[0], b2, b3);
                mma16816(acc[1][2 * j + 1], a[1], b2, b3);
            }
            {
                uint32_t e0, e1;
                ldmx2(e0, e1, qb + brx + kb);
                mma16816(acc[0][6], a[0], e0, e1);
                mma16816(acc[1][6], a[1], e0, e1);
            }
        }

        // A(kh+1) prefetch: STS phase into the other A buffer
        if (do_apref) {
            char* ab = smem + SM_A + ((kh + 1) & 1) * ABUF;
            const int base = qr * 1792;
#pragma unroll
            for (int j = 0; j < 7; ++j) {
                int i = base + j * NTHR + tid;
                if (i < IC_ * 136) {
                    int row = i / 136, col = i % 136;
                    __half hv = __float2half_rn(fpref[j]);
                    *(__half*)(ab + row * AROWB + col * 2) = hv;
                    if (col > 0)
                        *(__half*)(ab + ACOPY + row * AROWB + (col - 1) * 2) = hv;
                }
            }
        }
    }

    // ---- epilogue: bias + stores ----
#pragma unroll
    for (int m = 0; m < 2; ++m) {
        const int px = (wm * 2 + m) * 16 + g;
#pragma unroll
        for (int nc = 0; nc < 7; ++nc) {
            const int oc = (wn * 7 + nc) * 8 + c4;
            if (oc < OC_) {
                float bz0 = *(float*)(smem + SM_BIAS + oc * 4);
                float bz1 = *(float*)(smem + SM_BIAS + (oc + 1) * 4);
                size_t base0 = (((size_t)(b * OC_ + oc)) * OH_ + y) * OW_ + x0;
                size_t base1 = base0 + (size_t)OH_ * OW_;
                out[base0 + px]     = acc[m][nc][0] + bz0;
                out[base1 + px]     = acc[m][nc][1] + bz1;
                out[base0 + px + 8] = acc[m][nc][2] + bz0;
                out[base1 + px + 8] = acc[m][nc][3] + bz1;
            }
        }
    }
}

// ---------------- launch ----------------
extern "C" void kernel_launch(void* const* d_in, const int* in_sizes, int n_in,
                              void* d_out, int out_size) {
    const float* pic  = (const float*)d_in[0];   // [8,25,256,256]
    const float* wt   = (const float*)d_in[1];   // [100,25,9,9]
    const float* bias = (const float*)d_in[2];   // [100]
    float* out = (float*)d_out;                  // [8,100,248,248]

    int n = KH_ * 2 * 4 * NOC * QPITCH;
    prep_w<<<(n + 255) / 256, 256>>>(wt);

    cudaFuncSetAttribute(conv_hmma, cudaFuncAttributeMaxDynamicSharedMemorySize, SMEM_TOTAL);
    dim3 grid(2, OH_, B_);
    conv_hmma<<<grid, NTHR, SMEM_TOTAL>>>(pic, bias, out);
}

// round 9
// speedup vs baseline: 2.0363x; 1.6903x over previous
#include <cuda_runtime.h>
#include <cuda_fp16.h>
#include <cstdint>

// ---------------- problem constants ----------------
#define KH_ 9
#define KW_ 9
#define IC_ 25
#define OC_ 100
#define H_  256
#define W_  256
#define OH_ 248
#define OW_ 248
#define B_  8

// ---------------- GEMM config ----------------
#define KWP 10            // kw padded 9 -> 10
#define NOC 112           // oc padded 100 -> 112 (14 n8 chunks; 7 per warp-column)
#define MT  128           // pixels per tile
#define APITCH 144        // fp16 elems per ic row
#define AROWB (APITCH*2)  // 288 B
#define NTHR 256
#define NAROWS 26         // 25 ic + zero row for k-pad (k 250..255 -> ic 25)

// B quarter tiles: 64 k-elems, pitch 72 elems = 144 B (16B aligned, 4-bank stride)
#define QPITCH 72
#define QROWB  144
#define QTILE  (NOC*QROWB)       // 16128 B
#define NSEG   36                // 9 kh * 4 quarters (single fp16 pass)

// A buffer: even copy + odd-shift copy
#define ACOPY (NAROWS*AROWB)     // 7488
#define ABUF  (2*ACOPY)          // 14976

// smem layout (bytes)
#define SM_BIAS 0
#define SM_A    512                         // two A buffers (kh parity)
#define SM_B    (SM_A + 2*ABUF)             // 512 + 29952 = 30464
#define SMEM_TOTAL (SM_B + 3*QTILE)         // 30464 + 48384 = 78848 -> 2 CTAs/SM

// fp16 weights: [kh][quarter][oc][k_local(72)]
__device__ __align__(16) __half g_w[KH_][4][NOC][QPITCH];

// ---------------- helpers ----------------
__device__ __forceinline__ uint32_t smem_u32(const void* p) {
    uint32_t a;
    asm("{ .reg .u64 t; cvta.to.shared.u64 t, %1; cvt.u32.u64 %0, t; }" : "=r"(a) : "l"(p));
    return a;
}

__device__ __forceinline__ uint32_t lds32(uint32_t a) {
    uint32_t v;
    asm volatile("ld.shared.b32 %0, [%1];" : "=r"(v) : "r"(a));
    return v;
}

__device__ __forceinline__ void ldmx4(uint32_t& r0, uint32_t& r1, uint32_t& r2,
                                      uint32_t& r3, uint32_t addr) {
    asm volatile("ldmatrix.sync.aligned.m8n8.x4.shared.b16 {%0,%1,%2,%3}, [%4];"
                 : "=r"(r0), "=r"(r1), "=r"(r2), "=r"(r3) : "r"(addr));
}

__device__ __forceinline__ void ldmx2(uint32_t& r0, uint32_t& r1, uint32_t addr) {
    asm volatile("ldmatrix.sync.aligned.m8n8.x2.shared.b16 {%0,%1}, [%2];"
                 : "=r"(r0), "=r"(r1) : "r"(addr));
}

__device__ __forceinline__ void mma16816(float* d, const uint32_t* a,
                                         uint32_t b0, uint32_t b1) {
    asm volatile(
        "mma.sync.aligned.m16n8k16.row.col.f32.f16.f16.f32 "
        "{%0,%1,%2,%3}, {%4,%5,%6,%7}, {%8,%9}, {%0,%1,%2,%3};"
        : "+f"(d[0]), "+f"(d[1]), "+f"(d[2]), "+f"(d[3])
        : "r"(a[0]), "r"(a[1]), "r"(a[2]), "r"(a[3]), "r"(b0), "r"(b1));
}

// ---------------- weight prep ----------------
__global__ void prep_w(const float* __restrict__ wt) {
    int idx = blockIdx.x * blockDim.x + threadIdx.x;
    const int n = KH_ * 4 * NOC * QPITCH;
    if (idx >= n) return;
    int kh   = idx / (4 * NOC * QPITCH);
    int rem  = idx % (4 * NOC * QPITCH);
    int q    = rem / (NOC * QPITCH);      rem %= (NOC * QPITCH);
    int oc   = rem / QPITCH;
    int kl   = rem % QPITCH;
    float w = 0.f;
    int k = q * 64 + kl;
    if (oc < OC_ && kl < 64 && k < IC_ * KWP) {
        int ic = k / KWP, kw = k % KWP;
        if (kw < KW_)
            w = wt[(((size_t)oc * IC_ + ic) * KH_ + kh) * KW_ + kw];
    }
    g_w[kh][q][oc][kl] = __float2half_rn(w);
}

// ---------------- main kernel ----------------
// block = 128 px x 112 oc of one output row (b, y).
// 8 warps: wm = wid&3 (2 m16-frags), wn = wid>>2 (7 n8-chunks).
// 36 pipelined segments: seg s -> kh=s>>2, quarter=s&3.
__global__ __launch_bounds__(NTHR, 2)
void conv_hmma(const float* __restrict__ in,
               const float* __restrict__ bias,
               float* __restrict__ out) {
    extern __shared__ char smem[];
    const uint32_t sb = smem_u32(smem);
    const int tid = threadIdx.x;
    const int lid = tid & 31;
    const int wid = tid >> 5;
    const int wm = wid & 3;
    const int wn = wid >> 2;
    const int g  = lid >> 2;          // 0..7
    const int c4 = (lid & 3) << 1;    // 0,2,4,6
    const int x0 = blockIdx.x ? (OW_ - MT) : 0;
    const int y  = blockIdx.y;
    const int b  = blockIdx.z;

    // ---- init: zero both A buffers, stage bias ----
#pragma unroll 1
    for (int i = tid; i < (2 * ABUF) / 16; i += NTHR)
        *(uint4*)(smem + SM_A + i * 16) = make_uint4(0, 0, 0, 0);
    if (tid < NOC)
        *(float*)(smem + SM_BIAS + tid * 4) = (tid < OC_) ? bias[tid] : 0.f;
    __syncthreads();

    // ---- prologue: stage A(kh=0) into abuf0 ----
    {
        char* ab = smem + SM_A;   // buffer 0
#pragma unroll 1
        for (int i = tid; i < IC_ * 136; i += NTHR) {
            int row = i / 136, col = i % 136;
            float v = in[(((size_t)(b * IC_ + row)) * H_ + y) * W_ + x0 + col];
            __half hv = __float2half_rn(v);
            *(__half*)(ab + row * AROWB + col * 2) = hv;
            if (col > 0)
                *(__half*)(ab + ACOPY + row * AROWB + (col - 1) * 2) = hv;
        }
    }
    // ---- prologue: issue B groups for segments 0 and 1 ----
#pragma unroll
    for (int s = 0; s < 2; ++s) {
        const char* src = (const char*)(&g_w[0][s][0][0]);
        const uint32_t dst = sb + SM_B + (uint32_t)(s * QTILE);
#pragma unroll 1
        for (int i = tid; i < QTILE / 16; i += NTHR)
            asm volatile("cp.async.cg.shared.global [%0], [%1], 16;"
                         :: "r"(dst + (uint32_t)(i * 16)), "l"(src + i * 16));
        asm volatile("cp.async.commit_group;" ::: "memory");
    }

    // ldmatrix per-thread row/koff components (within a quarter tile)
    const int grp = lid >> 3;      // 0..3
    const int tr  = lid & 7;
    uint32_t bro[3];
#pragma unroll
    for (int j = 0; j < 3; ++j)
        bro[j] = (uint32_t)(((wn * 7 + 2 * j + (grp >> 1)) * 8 + tr) * QROWB
                            + (grp & 1) * 16);
    const uint32_t brx = (uint32_t)(((wn * 7 + 6) * 8 + (lid & 7)) * QROWB
                                    + ((lid >> 3) & 1) * 16);

    float acc[2][7][4];
#pragma unroll
    for (int m = 0; m < 2; ++m)
#pragma unroll
        for (int n = 0; n < 7; ++n)
#pragma unroll
            for (int q = 0; q < 4; ++q)
                acc[m][n][q] = 0.f;

    // ---- pipelined main loop ----
#pragma unroll 1
    for (int s = 0; s < NSEG; ++s) {
        const int kh   = s >> 2;
        const int qr   = s & 3;
        const bool do_apref = (qr < 2) && (kh < 8);

        if (s < NSEG - 2) {
            asm volatile("cp.async.wait_group 1;" ::: "memory");
        } else {
            asm volatile("cp.async.wait_group 0;" ::: "memory");
        }
        __syncthreads();

        // issue B prefetch for segment s+2 into ring slot (s+2)%3
        if (s + 2 < NSEG) {
            const int s2 = s + 2;
            const char* src = (const char*)(&g_w[s2 >> 2][s2 & 3][0][0]);
            const uint32_t dst = sb + SM_B + (uint32_t)((s2 % 3) * QTILE);
#pragma unroll 1
            for (int i = tid; i < QTILE / 16; i += NTHR)
                asm volatile("cp.async.cg.shared.global [%0], [%1], 16;"
                             :: "r"(dst + (uint32_t)(i * 16)), "l"(src + i * 16));
            asm volatile("cp.async.commit_group;" ::: "memory");
        }

        // A(kh+1) prefetch: LDG phase (before compute; STS after compute)
        float fpref[7];
        if (do_apref) {
            const int base = qr * 1792;
#pragma unroll
            for (int j = 0; j < 7; ++j) {
                int i = base + j * NTHR + tid;
                fpref[j] = 0.f;
                if (i < IC_ * 136) {
                    int row = i / 136, col = i % 136;
                    fpref[j] = in[(((size_t)(b * IC_ + row)) * H_ + (y + kh + 1)) * W_
                                  + x0 + col];
                }
            }
        }

        // ---- compute: 4 kc chunks on quarter qr ----
        const uint32_t abufb = sb + SM_A + (uint32_t)((kh & 1) * ABUF);
        const uint32_t abase = abufb + ((g & 1) ? (uint32_t)(ACOPY - 2) : 0u);
        uint32_t apx[2][2];
#pragma unroll
        for (int m = 0; m < 2; ++m)
#pragma unroll
            for (int h = 0; h < 2; ++h)
                apx[m][h] = abase + (uint32_t)(((wm * 2 + m) * 16 + g + h * 8) * 2);

        const uint32_t qb = sb + SM_B + (uint32_t)((s % 3) * QTILE);

#pragma unroll
        for (int kc = 0; kc < 4; ++kc) {
            const int k0 = qr * 64 + kc * 16 + c4;
            const int k1 = k0 + 8;
            const int ic0 = (k0 * 6554) >> 16;   // /10
            const int ic1 = (k1 * 6554) >> 16;
            const uint32_t koff0 = (uint32_t)(ic0 * AROWB + (k0 - ic0 * KWP) * 2);
            const uint32_t koff1 = (uint32_t)(ic1 * AROWB + (k1 - ic1 * KWP) * 2);

            uint32_t a[2][4];
#pragma unroll
            for (int m = 0; m < 2; ++m) {
                a[m][0] = lds32(apx[m][0] + koff0);
                a[m][1] = lds32(apx[m][1] + koff0);
                a[m][2] = lds32(apx[m][0] + koff1);
                a[m][3] = lds32(apx[m][1] + koff1);
            }

            const uint32_t kb = (uint32_t)(kc * 32);
#pragma unroll
            for (int j = 0; j < 3; ++j) {
                uint32_t b0, b1, b2, b3;
                ldmx4(b0, b1, b2, b3, qb + bro[j] + kb);
                mma16816(acc[0][2 * j],     a[0], b0, b1);
                mma16816(acc[1][2 * j],     a[1], b0, b1);
                mma16816(acc[0][2 * j + 1], a[0], b2, b3);
                mma16816(acc[1][2 * j + 1], a[1], b2, b3);
            }
            {
                uint32_t e0, e1;
                ldmx2(e0, e1, qb + brx + kb);
                mma16816(acc[0][6], a[0], e0, e1);
                mma16816(acc[1][6], a[1], e0, e1);
            }
        }

        // A(kh+1) prefetch: STS phase into the other A buffer
        if (do_apref) {
            char* ab = smem + SM_A + ((kh + 1) & 1) * ABUF;
            const int base = qr * 1792;
#pragma unroll
            for (int j = 0; j < 7; ++j) {
                int i = base + j * NTHR + tid;
                if (i < IC_ * 136) {
                    int row = i / 136, col = i % 136;
                    __half hv = __float2half_rn(fpref[j]);
                    *(__half*)(ab + row * AROWB + col * 2) = hv;
                    if (col > 0)
                        *(__half*)(ab + ACOPY + row * AROWB + (col - 1) * 2) = hv;
                }
            }
        }
    }

    // ---- epilogue: bias + stores ----
#pragma unroll
    for (int m = 0; m < 2; ++m) {
        const int px = (wm * 2 + m) * 16 + g;
#pragma unroll
        for (int nc = 0; nc < 7; ++nc) {
            const int oc = (wn * 7 + nc) * 8 + c4;
            if (oc < OC_) {
                float bz0 = *(float*)(smem + SM_BIAS + oc * 4);
                float bz1 = *(float*)(smem + SM_BIAS + (oc + 1) * 4);
                size_t base0 = (((size_t)(b * OC_ + oc)) * OH_ + y) * OW_ + x0;
                size_t base1 = base0 + (size_t)OH_ * OW_;
                out[base0 + px]     = acc[m][nc][0] + bz0;
                out[base1 + px]     = acc[m][nc][1] + bz1;
                out[base0 + px + 8] = acc[m][nc][2] + bz0;
                out[base1 + px + 8] = acc[m][nc][3] + bz1;
            }
        }
    }
}

// ---------------- launch ----------------
extern "C" void kernel_launch(void* const* d_in, const int* in_sizes, int n_in,
                              void* d_out, int out_size) {
    const float* pic  = (const float*)d_in[0];   // [8,25,256,256]
    const float* wt   = (const float*)d_in[1];   // [100,25,9,9]
    const float* bias = (const float*)d_in[2];   // [100]
    float* out = (float*)d_out;                  // [8,100,248,248]

    int n = KH_ * 4 * NOC * QPITCH;
    prep_w<<<(n + 255) / 256, 256>>>(wt);

    cudaFuncSetAttribute(conv_hmma, cudaFuncAttributeMaxDynamicSharedMemorySize, SMEM_TOTAL);
    dim3 grid(2, OH_, B_);
    conv_hmma<<<grid, NTHR, SMEM_TOTAL>>>(pic, bias, out);
}

// round 10
// speedup vs baseline: 2.4006x; 1.1789x over previous
#include <cuda_runtime.h>
#include <cuda_fp16.h>
#include <cstdint>

// ---------------- problem constants ----------------
#define KH_ 9
#define KW_ 9
#define IC_ 25
#define OC_ 100
#define H_  256
#define W_  256
#define OH_ 248
#define OW_ 248
#define B_  8

// ---------------- GEMM config ----------------
#define KWP 10            // kw padded 9 -> 10
#define NOC 104           // oc padded 100 -> 104 (13 n8 chunks: 7 + 6 per warp col)
#define MT  128           // pixels per tile
#define APITCH 144        // fp16 elems per ic row
#define AROWB (APITCH*2)  // 288 B
#define NTHR 256
#define NAROWS 26         // 25 ic + zero row for k-pad

// B quarter tiles: 64 k-elems, pitch 72 elems = 144 B
#define QPITCH 72
#define QROWB  144
#define QTILE  (NOC*QROWB)       // 14976 B
#define NSEG   36                // 9 kh * 4 quarters

// A buffer: even copy + odd-shift copy
#define ACOPY (NAROWS*AROWB)     // 7488
#define ABUF  (2*ACOPY)          // 14976
#define GA_P  264                // padded row length of pre-converted A

// smem layout (bytes)
#define SM_BIAS 0
#define SM_A    512                         // two A buffers (kh parity)
#define SM_B    (SM_A + 2*ABUF)             // 30464
#define SMEM_TOTAL (SM_B + 3*QTILE)         // 30464 + 44928 = 75392 -> 2 CTAs/SM

// fp16 weights: [kh][quarter][oc][k_local(72)]
__device__ __align__(16) __half g_w[KH_][4][NOC][QPITCH];
// pre-converted fp16 input, even + odd-shift parity copies
__device__ __align__(16) __half g_ae[B_][IC_][H_][GA_P];
__device__ __align__(16) __half g_ao[B_][IC_][H_][GA_P];

// ---------------- helpers ----------------
__device__ __forceinline__ uint32_t smem_u32(const void* p) {
    uint32_t a;
    asm("{ .reg .u64 t; cvta.to.shared.u64 t, %1; cvt.u32.u64 %0, t; }" : "=r"(a) : "l"(p));
    return a;
}

__device__ __forceinline__ uint32_t lds32(uint32_t a) {
    uint32_t v;
    asm volatile("ld.shared.b32 %0, [%1];" : "=r"(v) : "r"(a));
    return v;
}

__device__ __forceinline__ void ldmx4(uint32_t& r0, uint32_t& r1, uint32_t& r2,
                                      uint32_t& r3, uint32_t addr) {
    asm volatile("ldmatrix.sync.aligned.m8n8.x4.shared.b16 {%0,%1,%2,%3}, [%4];"
                 : "=r"(r0), "=r"(r1), "=r"(r2), "=r"(r3) : "r"(addr));
}

__device__ __forceinline__ void ldmx2(uint32_t& r0, uint32_t& r1, uint32_t addr) {
    asm volatile("ldmatrix.sync.aligned.m8n8.x2.shared.b16 {%0,%1}, [%2];"
                 : "=r"(r0), "=r"(r1) : "r"(addr));
}

__device__ __forceinline__ void mma16816(float* d, const uint32_t* a,
                                         uint32_t b0, uint32_t b1) {
    asm volatile(
        "mma.sync.aligned.m16n8k16.row.col.f32.f16.f16.f32 "
        "{%0,%1,%2,%3}, {%4,%5,%6,%7}, {%8,%9}, {%0,%1,%2,%3};"
        : "+f"(d[0]), "+f"(d[1]), "+f"(d[2]), "+f"(d[3])
        : "r"(a[0]), "r"(a[1]), "r"(a[2]), "r"(a[3]), "r"(b0), "r"(b1));
}

__device__ __forceinline__ void cpasync16(uint32_t dst, const void* src) {
    asm volatile("cp.async.cg.shared.global [%0], [%1], 16;"
                 :: "r"(dst), "l"(src));
}

// ---------------- prep: weights ----------------
__global__ void prep_w(const float* __restrict__ wt) {
    int idx = blockIdx.x * blockDim.x + threadIdx.x;
    const int n = KH_ * 4 * NOC * QPITCH;
    if (idx >= n) return;
    int kh   = idx / (4 * NOC * QPITCH);
    int rem  = idx % (4 * NOC * QPITCH);
    int q    = rem / (NOC * QPITCH);      rem %= (NOC * QPITCH);
    int oc   = rem / QPITCH;
    int kl   = rem % QPITCH;
    float w = 0.f;
    int k = q * 64 + kl;
    if (oc < OC_ && kl < 64 && k < IC_ * KWP) {
        int ic = k / KWP, kw = k % KWP;
        if (kw < KW_)
            w = wt[(((size_t)oc * IC_ + ic) * KH_ + kh) * KW_ + kw];
    }
    g_w[kh][q][oc][kl] = __float2half_rn(w);
}

// ---------------- prep: input fp16 parity copies ----------------
__global__ void prep_a(const float* __restrict__ pic) {
    const long long total = (long long)B_ * IC_ * H_ * GA_P;
    long long idx = (long long)blockIdx.x * blockDim.x + threadIdx.x;
    if (idx >= total) return;
    int c    = (int)(idx % GA_P);
    long long r = idx / GA_P;        // (b*IC + ic)*H + row
    const float* prow = pic + r * W_;
    __half ve = __float2half_rn(c < W_ ? prow[c] : 0.f);
    __half vo = __float2half_rn(c + 1 < W_ ? prow[c + 1] : 0.f);
    ((__half*)g_ae)[idx] = ve;
    ((__half*)g_ao)[idx] = vo;
}

// ---------------- main kernel ----------------
// block = 128 px x 104 oc of one output row (b, y).
// 8 warps: wm = wid&3 (2 m16-frags), wn = wid>>2 (7 or 6 n8-chunks).
// 36 pipelined segments: seg s -> kh=s>>2, quarter=s&3; ring-3 B quarters,
// A double-buffered by kh parity, all staging via cp.async (distance 2).
__global__ __launch_bounds__(NTHR, 2)
void conv_hmma(const float* __restrict__ bias,
               float* __restrict__ out) {
    extern __shared__ char smem[];
    const uint32_t sb = smem_u32(smem);
    const int tid = threadIdx.x;
    const int lid = tid & 31;
    const int wid = tid >> 5;
    const int wm = wid & 3;
    const int wn = wid >> 2;
    const int g  = lid >> 2;          // 0..7
    const int c4 = (lid & 3) << 1;    // 0,2,4,6
    const int x0 = blockIdx.x ? (OW_ - MT) : 0;
    const int y  = blockIdx.y;
    const int b  = blockIdx.z;

    // ---- init: zero both A buffers (pads + zero row persist), stage bias ----
#pragma unroll 1
    for (int i = tid; i < (2 * ABUF) / 16; i += NTHR)
        *(uint4*)(smem + SM_A + i * 16) = make_uint4(0, 0, 0, 0);
    if (tid < NOC)
        *(float*)(smem + SM_BIAS + tid * 4) = (tid < OC_) ? bias[tid] : 0.f;
    __syncthreads();   // zeroing visible before cp.async overwrites data region

    // ---- prologue: group 0 = A(kh=0) + B(seg 0); group 1 = B(seg 1) ----
    {
        // A(0): 2 parities * 25 ic * 17 x 16B
#pragma unroll 1
        for (int i = tid; i < 2 * IC_ * 17; i += NTHR) {
            int p  = i / (IC_ * 17);
            int r  = i % (IC_ * 17);
            int ic = r / 17;
            int ch = r % 17;
            const __half* src = (p ? &g_ao[0][0][0][0] : &g_ae[0][0][0][0])
                + ((((size_t)b * IC_ + ic) * H_) + y) * GA_P + x0 + ch * 8;
            cpasync16(sb + SM_A + (uint32_t)(p * ACOPY + ic * AROWB + ch * 16), src);
        }
        // B(seg 0)
#pragma unroll 1
        for (int i = tid; i < QTILE / 16; i += NTHR)
            cpasync16(sb + SM_B + (uint32_t)(i * 16), (const char*)(&g_w[0][0][0][0]) + i * 16);
        asm volatile("cp.async.commit_group;" ::: "memory");
        // B(seg 1)
#pragma unroll 1
        for (int i = tid; i < QTILE / 16; i += NTHR)
            cpasync16(sb + SM_B + (uint32_t)(QTILE + i * 16),
                      (const char*)(&g_w[0][1][0][0]) + i * 16);
        asm volatile("cp.async.commit_group;" ::: "memory");
    }

    // ldmatrix per-thread addresses (within a quarter tile)
    const int cb0 = wn * 7;        // base n8 chunk: 0 (7 chunks) or 7 (6 chunks)
    const int grp = lid >> 3;      // 0..3
    const int tr  = lid & 7;
    uint32_t bro[3];
#pragma unroll
    for (int j = 0; j < 3; ++j)
        bro[j] = (uint32_t)(((cb0 + 2 * j + (grp >> 1)) * 8 + tr) * QROWB
                            + (grp & 1) * 16);
    const uint32_t brx = (uint32_t)((6 * 8 + (lid & 7)) * QROWB
                                    + ((lid >> 3) & 1) * 16);   // chunk 6 (wn0 only)

    float acc[2][7][4];
#pragma unroll
    for (int m = 0; m < 2; ++m)
#pragma unroll
        for (int n = 0; n < 7; ++n)
#pragma unroll
            for (int q = 0; q < 4; ++q)
                acc[m][n][q] = 0.f;

    // ---- pipelined main loop ----
#pragma unroll 1
    for (int s = 0; s < NSEG; ++s) {
        const int kh = s >> 2;
        const int qr = s & 3;

        if (s < NSEG - 2) {
            asm volatile("cp.async.wait_group 1;" ::: "memory");
        } else {
            asm volatile("cp.async.wait_group 0;" ::: "memory");
        }
        __syncthreads();

        // issue prefetch group for segment s+2 (B quarter + A when kh advances)
        if (s + 2 < NSEG) {
            const int s2 = s + 2;
            const char* bsrc = (const char*)(&g_w[s2 >> 2][s2 & 3][0][0]);
            const uint32_t bdst = sb + SM_B + (uint32_t)((s2 % 3) * QTILE);
#pragma unroll 1
            for (int i = tid; i < QTILE / 16; i += NTHR)
                cpasync16(bdst + (uint32_t)(i * 16), bsrc + i * 16);
            if ((s2 & 3) == 0) {
                const int kh2 = s2 >> 2;
                const uint32_t adst = sb + SM_A + (uint32_t)((kh2 & 1) * ABUF);
#pragma unroll 1
                for (int i = tid; i < 2 * IC_ * 17; i += NTHR) {
                    int p  = i / (IC_ * 17);
                    int r  = i % (IC_ * 17);
                    int ic = r / 17;
                    int ch = r % 17;
                    const __half* src = (p ? &g_ao[0][0][0][0] : &g_ae[0][0][0][0])
                        + ((((size_t)b * IC_ + ic) * H_) + (y + kh2)) * GA_P + x0 + ch * 8;
                    cpasync16(adst + (uint32_t)(p * ACOPY + ic * AROWB + ch * 16), src);
                }
            }
            asm volatile("cp.async.commit_group;" ::: "memory");
        }

        // ---- compute: 4 kc chunks on quarter qr ----
        const uint32_t abufb = sb + SM_A + (uint32_t)((kh & 1) * ABUF);
        const uint32_t abase = abufb + ((g & 1) ? (uint32_t)(ACOPY - 2) : 0u);
        uint32_t apx[2][2];
#pragma unroll
        for (int m = 0; m < 2; ++m)
#pragma unroll
            for (int h = 0; h < 2; ++h)
                apx[m][h] = abase + (uint32_t)(((wm * 2 + m) * 16 + g + h * 8) * 2);

        const uint32_t qb = sb + SM_B + (uint32_t)((s % 3) * QTILE);

#pragma unroll
        for (int kc = 0; kc < 4; ++kc) {
            const int k0 = qr * 64 + kc * 16 + c4;
            const int k1 = k0 + 8;
            const int ic0 = (k0 * 6554) >> 16;   // /10
            const int ic1 = (k1 * 6554) >> 16;
            const uint32_t koff0 = (uint32_t)(ic0 * AROWB + (k0 - ic0 * KWP) * 2);
            const uint32_t koff1 = (uint32_t)(ic1 * AROWB + (k1 - ic1 * KWP) * 2);

            uint32_t a[2][4];
#pragma unroll
            for (int m = 0; m < 2; ++m) {
                a[m][0] = lds32(apx[m][0] + koff0);
                a[m][1] = lds32(apx[m][1] + koff0);
                a[m][2] = lds32(apx[m][0] + koff1);
                a[m][3] = lds32(apx[m][1] + koff1);
            }

            const uint32_t kb = (uint32_t)(kc * 32);
#pragma unroll
            for (int j = 0; j < 3; ++j) {
                uint32_t b0, b1, b2, b3;
                ldmx4(b0, b1, b2, b3, qb + bro[j] + kb);
                mma16816(acc[0][2 * j],     a[0], b0, b1);
                mma16816(acc[1][2 * j],     a[1], b0, b1);
                mma16816(acc[0][2 * j + 1], a[0], b2, b3);
                mma16816(acc[1][2 * j + 1], a[1], b2, b3);
            }
            if (wn == 0) {  // 7th chunk, first warp column only
                uint32_t e0, e1;
                ldmx2(e0, e1, qb + brx + kb);
                mma16816(acc[0][6], a[0], e0, e1);
                mma16816(acc[1][6], a[1], e0, e1);
            }
        }
    }

    // ---- epilogue: bias + stores ----
    const int nchunks = (wn == 0) ? 7 : 6;
#pragma unroll
    for (int m = 0; m < 2; ++m) {
        const int px = (wm * 2 + m) * 16 + g;
#pragma unroll
        for (int nc = 0; nc < 7; ++nc) {
            if (nc >= nchunks) break;
            const int oc = (cb0 + nc) * 8 + c4;
            if (oc < OC_) {
                float bz0 = *(float*)(smem + SM_BIAS + oc * 4);
                float bz1 = *(float*)(smem + SM_BIAS + (oc + 1) * 4);
                size_t base0 = (((size_t)(b * OC_ + oc)) * OH_ + y) * OW_ + x0;
                size_t base1 = base0 + (size_t)OH_ * OW_;
                out[base0 + px]     = acc[m][nc][0] + bz0;
                out[base1 + px]     = acc[m][nc][1] + bz1;
                out[base0 + px + 8] = acc[m][nc][2] + bz0;
                out[base1 + px + 8] = acc[m][nc][3] + bz1;
            }
        }
    }
}

// ---------------- launch ----------------
extern "C" void kernel_launch(void* const* d_in, const int* in_sizes, int n_in,
                              void* d_out, int out_size) {
    const float* pic  = (const float*)d_in[0];   // [8,25,256,256]
    const float* wt   = (const float*)d_in[1];   // [100,25,9,9]
    const float* bias = (const float*)d_in[2];   // [100]
    float* out = (float*)d_out;                  // [8,100,248,248]

    int nw = KH_ * 4 * NOC * QPITCH;
    prep_w<<<(nw + 255) / 256, 256>>>(wt);
    long long na = (long long)B_ * IC_ * H_ * GA_P;
    prep_a<<<(int)((na + 255) / 256), 256>>>(pic);

    cudaFuncSetAttribute(conv_hmma, cudaFuncAttributeMaxDynamicSharedMemorySize, SMEM_TOTAL);
    dim3 grid(2, OH_, B_);
    conv_hmma<<<grid, NTHR, SMEM_TOTAL>>>(bias, out);
}